// round 7
// baseline (speedup 1.0000x reference)
#include <cuda_runtime.h>
#include <cuda_bf16.h>
#include <cstdint>
#include <cstddef>

// Problem constants
#define Bb 4
#define Tt 1024
#define Cc 1024
#define Hh 16
#define Dd 64
#define Mm 4096      // B*T tokens
#define FF 4096      // ffn hidden

// ---------------- scratch (device globals; no allocation) ----------------
__device__ float g_h[Mm * Cc];
__device__ float g_q[Mm * Cc];
__device__ float g_k[Mm * Cc];
__device__ float g_v[Mm * Cc];
__device__ float g_attn[Mm * Cc];
__device__ float g_ffh[Mm * FF];

// ---------------- helpers ----------------
__device__ __forceinline__ void cp16(void* dst_smem, const void* src) {
    uint32_t sa = (uint32_t)__cvta_generic_to_shared(dst_smem);
    asm volatile("cp.async.cg.shared.global [%0], [%1], 16;\n" :: "r"(sa), "l"(src));
}
__device__ __forceinline__ void mma_tf32(float c[4], const uint32_t a[4], const uint32_t b[2]) {
    asm volatile(
        "mma.sync.aligned.m16n8k8.row.col.f32.tf32.tf32.f32 "
        "{%0,%1,%2,%3}, {%4,%5,%6,%7}, {%8,%9}, {%0,%1,%2,%3};\n"
        : "+f"(c[0]), "+f"(c[1]), "+f"(c[2]), "+f"(c[3])
        : "r"(a[0]), "r"(a[1]), "r"(a[2]), "r"(a[3]), "r"(b[0]), "r"(b[1]));
}
__device__ __forceinline__ uint32_t fau(float x) { return __float_as_uint(x); }

// ---------------- block reduction ----------------
__device__ __forceinline__ float block_sum_256(float v) {
    __shared__ float sh[8];
    const int lane = threadIdx.x & 31;
    const int w = threadIdx.x >> 5;
#pragma unroll
    for (int o = 16; o > 0; o >>= 1) v += __shfl_xor_sync(0xffffffffu, v, o);
    if (lane == 0) sh[w] = v;
    __syncthreads();
    float r = (lane < 8) ? sh[lane] : 0.f;
#pragma unroll
    for (int o = 4; o > 0; o >>= 1) r += __shfl_xor_sync(0xffffffffu, r, o);
    float total = __shfl_sync(0xffffffffu, r, 0);
    __syncthreads();
    return total;
}

// ---------------- layernorm ----------------
__global__ __launch_bounds__(256)
void ln_kernel(const float* __restrict__ x, const float* __restrict__ g,
               const float* __restrict__ b, float* __restrict__ out) {
    const size_t row = blockIdx.x;
    const int t = threadIdx.x;
    const float4 v = ((const float4*)(x + row * Cc))[t];
    float s = v.x + v.y + v.z + v.w;
    const float mean = block_sum_256(s) * (1.f / Cc);
    const float dx = v.x - mean, dy = v.y - mean, dz = v.z - mean, dw = v.w - mean;
    const float var = block_sum_256(dx*dx + dy*dy + dz*dz + dw*dw) * (1.f / Cc);
    const float inv = rsqrtf(var + 1e-5f);
    const float4 gg = ((const float4*)g)[t];
    const float4 bb = ((const float4*)b)[t];
    float4 o;
    o.x = dx * inv * gg.x + bb.x;
    o.y = dy * inv * gg.y + bb.y;
    o.z = dz * inv * gg.z + bb.z;
    o.w = dw * inv * gg.w + bb.w;
    ((float4*)(out + row * Cc))[t] = o;
}

// ---------------- tf32 tensor-core GEMM ----------------
// CTA tile 128x128, 128 thr = 4 warps (2m x 2n), warp tile 64x64.
// K-tile 32, 3-stage cp.async pipeline. Raw fp32 bits into tf32 MMA.
#define LDA_S 36
#define LDB_S 136
#define A_SZ (128 * LDA_S)
#define B_SZ (32 * LDB_S)
#define STG_SZ (A_SZ + B_SZ)
#define GEMM_SMEM (3 * STG_SZ * 4)

template<bool RELU, bool RES>
__global__ __launch_bounds__(128, 2)
void gemm_tc(const float* __restrict__ A, const float* __restrict__ W,
             const float* __restrict__ bias, const float* __restrict__ res,
             float* __restrict__ out, int M, int N, int K) {
    extern __shared__ float smx[];
    // stage s: A at smx + s*STG_SZ, B at smx + s*STG_SZ + A_SZ

    const int m0 = blockIdx.y * 128;
    const int n0 = blockIdx.x * 128;
    const int t = threadIdx.x;
    const int lane = t & 31;
    const int wid = t >> 5;
    const int g = lane >> 2;
    const int tig = lane & 3;
    const int wm = (wid & 1) * 64;
    const int wn = (wid >> 1) * 64;

    // loader mapping (128 threads)
    const int ar = t >> 3;           // 0..15, rows ar + i*16 (i<8)
    const int ak = (t & 7) * 4;
    const int brr = t >> 5;          // 0..3,  rows brr + i*4 (i<8)
    const int bn = (t & 31) * 4;

    const float* Agp = A + (size_t)(m0 + ar) * K + ak;
    const float* Wgp = W + (size_t)brr * N + n0 + bn;

    float acc[4][8][4];
#pragma unroll
    for (int mi = 0; mi < 4; mi++)
#pragma unroll
        for (int ni = 0; ni < 8; ni++)
#pragma unroll
            for (int r = 0; r < 4; r++) acc[mi][ni][r] = 0.f;

    const int ntiles = K >> 5;   // >= 32 for all our shapes

    // prefetch tiles 0 and 1
#pragma unroll
    for (int pf = 0; pf < 2; pf++) {
        float* Apt = smx + pf * STG_SZ;
        float* Bpt = Apt + A_SZ;
        const int koff = pf * 32;
#pragma unroll
        for (int i = 0; i < 8; i++)
            cp16(Apt + (ar + i * 16) * LDA_S + ak, Agp + koff + (size_t)i * 16 * K);
#pragma unroll
        for (int i = 0; i < 8; i++)
            cp16(Bpt + (brr + i * 4) * LDB_S + bn, Wgp + (size_t)(koff + i * 4) * N);
        asm volatile("cp.async.commit_group;\n");
    }

    int buf = 0;
    for (int kt = 0; kt < ntiles; kt++) {
        if (kt + 1 < ntiles) {
            asm volatile("cp.async.wait_group 1;\n");
        } else {
            asm volatile("cp.async.wait_group 0;\n");
        }
        __syncthreads();   // tile kt visible to all; everyone done reading buf (kt+2)%3

        if (kt + 2 < ntiles) {
            const int pb = (buf + 2 >= 3) ? buf - 1 : buf + 2;
            float* Apt = smx + pb * STG_SZ;
            float* Bpt = Apt + A_SZ;
            const int koff = (kt + 2) * 32;
#pragma unroll
            for (int i = 0; i < 8; i++)
                cp16(Apt + (ar + i * 16) * LDA_S + ak, Agp + koff + (size_t)i * 16 * K);
#pragma unroll
            for (int i = 0; i < 8; i++)
                cp16(Bpt + (brr + i * 4) * LDB_S + bn, Wgp + (size_t)(koff + i * 4) * N);
            asm volatile("cp.async.commit_group;\n");
        }

        const float* Apt = smx + buf * STG_SZ;
        const float* Bpt = Apt + A_SZ;
#pragma unroll
        for (int kk = 0; kk < 4; kk++) {
            uint32_t af[4][4];
#pragma unroll
            for (int mi = 0; mi < 4; mi++) {
                const float* p = Apt + (wm + mi * 16 + g) * LDA_S + kk * 8 + tig;
                af[mi][0] = fau(p[0]);
                af[mi][1] = fau(p[8 * LDA_S]);
                af[mi][2] = fau(p[4]);
                af[mi][3] = fau(p[8 * LDA_S + 4]);
            }
            uint32_t bf[8][2];
#pragma unroll
            for (int ni = 0; ni < 8; ni++) {
                const float* p = Bpt + (kk * 8 + tig) * LDB_S + wn + ni * 8 + g;
                bf[ni][0] = fau(p[0]);
                bf[ni][1] = fau(p[4 * LDB_S]);
            }
#pragma unroll
            for (int mi = 0; mi < 4; mi++)
#pragma unroll
                for (int ni = 0; ni < 8; ni++)
                    mma_tf32(acc[mi][ni], af[mi], bf[ni]);
        }
        buf = (buf + 1 == 3) ? 0 : buf + 1;
    }

#pragma unroll
    for (int mi = 0; mi < 4; mi++) {
        const int m = m0 + wm + mi * 16 + g;
#pragma unroll
        for (int ni = 0; ni < 8; ni++) {
            const int n = n0 + wn + ni * 8 + tig * 2;
            float2 v0 = make_float2(acc[mi][ni][0], acc[mi][ni][1]);
            float2 v1 = make_float2(acc[mi][ni][2], acc[mi][ni][3]);
            if (bias) {
                const float b0 = bias[n], b1 = bias[n + 1];
                v0.x += b0; v0.y += b1;
                v1.x += b0; v1.y += b1;
            }
            if (RES) {
                const float2 r0 = *(const float2*)(res + (size_t)m * N + n);
                const float2 r1 = *(const float2*)(res + (size_t)(m + 8) * N + n);
                v0.x += r0.x; v0.y += r0.y;
                v1.x += r1.x; v1.y += r1.y;
            }
            if (RELU) {
                v0.x = fmaxf(v0.x, 0.f); v0.y = fmaxf(v0.y, 0.f);
                v1.x = fmaxf(v1.x, 0.f); v1.y = fmaxf(v1.y, 0.f);
            }
            *(float2*)(out + (size_t)m * N + n) = v0;
            *(float2*)(out + (size_t)(m + 8) * N + n) = v1;
        }
    }
}

// ---------------- tensor-core flash attention ----------------
#define QP 68
#define VP 72
#define Q_SZ (64 * QP)
#define K_SZ (64 * QP)
#define V_SZ (64 * VP)
#define P_SZ (16 * QP)
#define ATTN_SMEM ((Q_SZ + 2 * K_SZ + 2 * V_SZ + 4 * P_SZ) * 4)

template<bool CAUSAL>
__global__ __launch_bounds__(128)
void attn_tc(const float* __restrict__ Qg, const float* __restrict__ Kg,
             const float* __restrict__ Vg, float* __restrict__ Og) {
    extern __shared__ float sm[];
    float* Qs = sm;
    float* Ks = sm + Q_SZ;
    float* Vs = Ks + 2 * K_SZ;
    float* Ps = Vs + 2 * V_SZ;

    const int qt = blockIdx.x;
    const int bh = blockIdx.y;
    const int b = bh >> 4;
    const int h = bh & 15;
    const int q0 = qt * 64;
    const int t = threadIdx.x;
    const int lane = t & 31;
    const int w = t >> 5;
    const int g = lane >> 2;
    const int tig = lane & 3;
    const int wm = w * 16;
    const int lr = t >> 4;
    const int lc = (t & 15) * 4;

    const float* Qbase = Qg + ((size_t)(b * Tt + q0)) * Cc + h * Dd;
    const float* Kbase = Kg + ((size_t)(b * Tt)) * Cc + h * Dd;
    const float* Vbase = Vg + ((size_t)(b * Tt)) * Cc + h * Dd;

#pragma unroll
    for (int i = 0; i < 8; i++)
        cp16(Qs + (lr + i * 8) * QP + lc, Qbase + (size_t)(lr + i * 8) * Cc + lc);
#pragma unroll
    for (int i = 0; i < 8; i++) {
        cp16(Ks + (lr + i * 8) * QP + lc, Kbase + (size_t)(lr + i * 8) * Cc + lc);
        cp16(Vs + (lr + i * 8) * VP + lc, Vbase + (size_t)(lr + i * 8) * Cc + lc);
    }
    asm volatile("cp.async.commit_group;\n");

    float m0r = -1e30f, m1r = -1e30f, l0 = 0.f, l1 = 0.f;
    float oacc[8][4];
#pragma unroll
    for (int nf = 0; nf < 8; nf++)
#pragma unroll
        for (int r = 0; r < 4; r++) oacc[nf][r] = 0.f;

    const int ktend = CAUSAL ? qt : (Tt / 64 - 1);
    for (int kt = 0; kt <= ktend; kt++) {
        const int buf = kt & 1;
        if (kt < ktend) {
            const float* Kp = Kbase + (size_t)(kt + 1) * 64 * Cc;
            const float* Vp = Vbase + (size_t)(kt + 1) * 64 * Cc;
            float* Kd = Ks + (buf ^ 1) * K_SZ;
            float* Vd = Vs + (buf ^ 1) * V_SZ;
#pragma unroll
            for (int i = 0; i < 8; i++) {
                cp16(Kd + (lr + i * 8) * QP + lc, Kp + (size_t)(lr + i * 8) * Cc + lc);
                cp16(Vd + (lr + i * 8) * VP + lc, Vp + (size_t)(lr + i * 8) * Cc + lc);
            }
            asm volatile("cp.async.commit_group;\n");
            asm volatile("cp.async.wait_group 1;\n");
        } else {
            asm volatile("cp.async.wait_group 0;\n");
        }
        __syncthreads();

        const float* Kb = Ks + buf * K_SZ;
        const float* Vb = Vs + buf * V_SZ;

        float sc[8][4];
#pragma unroll
        for (int nf = 0; nf < 8; nf++)
#pragma unroll
            for (int r = 0; r < 4; r++) sc[nf][r] = 0.f;
#pragma unroll
        for (int kk = 0; kk < 8; kk++) {
            uint32_t a[4];
            const float* qp = Qs + (wm + g) * QP + kk * 8 + tig;
            a[0] = fau(qp[0]);
            a[1] = fau(qp[8 * QP]);
            a[2] = fau(qp[4]);
            a[3] = fau(qp[8 * QP + 4]);
#pragma unroll
            for (int nf = 0; nf < 8; nf++) {
                uint32_t bb[2];
                const float* kp = Kb + (nf * 8 + g) * QP + kk * 8 + tig;
                bb[0] = fau(kp[0]);
                bb[1] = fau(kp[4]);
                mma_tf32(sc[nf], a, bb);
            }
        }

        const int r0g = q0 + wm + g;
        const int r1g = r0g + 8;
#pragma unroll
        for (int nf = 0; nf < 8; nf++) {
            sc[nf][0] *= 0.125f; sc[nf][1] *= 0.125f;
            sc[nf][2] *= 0.125f; sc[nf][3] *= 0.125f;
            if (CAUSAL && kt == qt) {
                const int c0 = kt * 64 + nf * 8 + tig * 2;
                if (c0 > r0g) sc[nf][0] = -1e30f;
                if (c0 + 1 > r0g) sc[nf][1] = -1e30f;
                if (c0 > r1g) sc[nf][2] = -1e30f;
                if (c0 + 1 > r1g) sc[nf][3] = -1e30f;
            }
        }

        float mx0 = -1e30f, mx1 = -1e30f;
#pragma unroll
        for (int nf = 0; nf < 8; nf++) {
            mx0 = fmaxf(mx0, fmaxf(sc[nf][0], sc[nf][1]));
            mx1 = fmaxf(mx1, fmaxf(sc[nf][2], sc[nf][3]));
        }
        mx0 = fmaxf(mx0, __shfl_xor_sync(0xffffffffu, mx0, 1));
        mx0 = fmaxf(mx0, __shfl_xor_sync(0xffffffffu, mx0, 2));
        mx1 = fmaxf(mx1, __shfl_xor_sync(0xffffffffu, mx1, 1));
        mx1 = fmaxf(mx1, __shfl_xor_sync(0xffffffffu, mx1, 2));
        const float nm0 = fmaxf(m0r, mx0);
        const float nm1 = fmaxf(m1r, mx1);
        const float al0 = __expf(m0r - nm0);
        const float al1 = __expf(m1r - nm1);
        float rs0 = 0.f, rs1 = 0.f;
#pragma unroll
        for (int nf = 0; nf < 8; nf++) {
            sc[nf][0] = __expf(sc[nf][0] - nm0);
            sc[nf][1] = __expf(sc[nf][1] - nm0);
            sc[nf][2] = __expf(sc[nf][2] - nm1);
            sc[nf][3] = __expf(sc[nf][3] - nm1);
            rs0 += sc[nf][0] + sc[nf][1];
            rs1 += sc[nf][2] + sc[nf][3];
        }
        rs0 += __shfl_xor_sync(0xffffffffu, rs0, 1);
        rs0 += __shfl_xor_sync(0xffffffffu, rs0, 2);
        rs1 += __shfl_xor_sync(0xffffffffu, rs1, 1);
        rs1 += __shfl_xor_sync(0xffffffffu, rs1, 2);
        l0 = l0 * al0 + rs0;
        l1 = l1 * al1 + rs1;
        m0r = nm0; m1r = nm1;
#pragma unroll
        for (int nf = 0; nf < 8; nf++) {
            oacc[nf][0] *= al0; oacc[nf][1] *= al0;
            oacc[nf][2] *= al1; oacc[nf][3] *= al1;
        }

        float* Pw = Ps + w * P_SZ;
#pragma unroll
        for (int nf = 0; nf < 8; nf++) {
            *(float2*)&Pw[g * QP + nf * 8 + tig * 2] = make_float2(sc[nf][0], sc[nf][1]);
            *(float2*)&Pw[(g + 8) * QP + nf * 8 + tig * 2] = make_float2(sc[nf][2], sc[nf][3]);
        }
        __syncwarp();

#pragma unroll
        for (int kk = 0; kk < 8; kk++) {
            uint32_t a[4];
            const float* pp = Pw + g * QP + kk * 8 + tig;
            a[0] = fau(pp[0]);
            a[1] = fau(pp[8 * QP]);
            a[2] = fau(pp[4]);
            a[3] = fau(pp[8 * QP + 4]);
#pragma unroll
            for (int nf = 0; nf < 8; nf++) {
                uint32_t bb[2];
                const float* vp = Vb + (kk * 8 + tig) * VP + nf * 8 + g;
                bb[0] = fau(vp[0]);
                bb[1] = fau(vp[4 * VP]);
                mma_tf32(oacc[nf], a, bb);
            }
        }
        __syncthreads();
    }

    const float inv0 = 1.f / l0;
    const float inv1 = 1.f / l1;
    float* orow0 = Og + ((size_t)(b * Tt + q0 + wm + g)) * Cc + h * Dd;
    float* orow1 = orow0 + (size_t)8 * Cc;
#pragma unroll
    for (int nf = 0; nf < 8; nf++) {
        *(float2*)&orow0[nf * 8 + tig * 2] = make_float2(oacc[nf][0] * inv0, oacc[nf][1] * inv0);
        *(float2*)&orow1[nf * 8 + tig * 2] = make_float2(oacc[nf][2] * inv1, oacc[nf][3] * inv1);
    }
}

// ---------------- driver ----------------
extern "C" void kernel_launch(void* const* d_in, const int* in_sizes, int n_in,
                              void* d_out, int out_size) {
    const float* x      = (const float*)d_in[0];
    const float* enc    = (const float*)d_in[1];
    const float* sa_wq  = (const float*)d_in[2];
    const float* sa_wk  = (const float*)d_in[3];
    const float* sa_wv  = (const float*)d_in[4];
    const float* sa_wo  = (const float*)d_in[5];
    const float* sa_bo  = (const float*)d_in[6];
    const float* ca_wq  = (const float*)d_in[7];
    const float* ca_wk  = (const float*)d_in[8];
    const float* ca_wv  = (const float*)d_in[9];
    const float* ca_wo  = (const float*)d_in[10];
    const float* ca_bo  = (const float*)d_in[11];
    const float* ff_w1  = (const float*)d_in[12];
    const float* ff_b1  = (const float*)d_in[13];
    const float* ff_w2  = (const float*)d_in[14];
    const float* ff_b2  = (const float*)d_in[15];
    const float* ln1_g  = (const float*)d_in[16];
    const float* ln1_b  = (const float*)d_in[17];
    const float* ln2_g  = (const float*)d_in[18];
    const float* ln2_b  = (const float*)d_in[19];
    const float* ln3_g  = (const float*)d_in[20];
    const float* ln3_b  = (const float*)d_in[21];
    float* out = (float*)d_out;

    float *h, *q, *k, *v, *a, *ff;
    cudaGetSymbolAddress((void**)&h,  g_h);
    cudaGetSymbolAddress((void**)&q,  g_q);
    cudaGetSymbolAddress((void**)&k,  g_k);
    cudaGetSymbolAddress((void**)&v,  g_v);
    cudaGetSymbolAddress((void**)&a,  g_attn);
    cudaGetSymbolAddress((void**)&ff, g_ffh);

    cudaFuncSetAttribute((const void*)attn_tc<true>,
                         cudaFuncAttributeMaxDynamicSharedMemorySize, ATTN_SMEM);
    cudaFuncSetAttribute((const void*)attn_tc<false>,
                         cudaFuncAttributeMaxDynamicSharedMemorySize, ATTN_SMEM);
    cudaFuncSetAttribute((const void*)gemm_tc<false, false>,
                         cudaFuncAttributeMaxDynamicSharedMemorySize, GEMM_SMEM);
    cudaFuncSetAttribute((const void*)gemm_tc<false, true>,
                         cudaFuncAttributeMaxDynamicSharedMemorySize, GEMM_SMEM);
    cudaFuncSetAttribute((const void*)gemm_tc<true, false>,
                         cudaFuncAttributeMaxDynamicSharedMemorySize, GEMM_SMEM);

    const dim3 gP(Cc / 128, Mm / 128);    // projections / FFN2: 8 x 32
    const dim3 gF1(FF / 128, Mm / 128);   // FFN1: 32 x 32
    const dim3 gA(Tt / 64, Bb * Hh);

    // ---- self-attention block ----
    ln_kernel<<<Mm, 256>>>(x, ln1_g, ln1_b, h);
    gemm_tc<false, false><<<gP, 128, GEMM_SMEM>>>(h, sa_wq, nullptr, nullptr, q, Mm, Cc, Cc);
    gemm_tc<false, false><<<gP, 128, GEMM_SMEM>>>(h, sa_wk, nullptr, nullptr, k, Mm, Cc, Cc);
    gemm_tc<false, false><<<gP, 128, GEMM_SMEM>>>(h, sa_wv, nullptr, nullptr, v, Mm, Cc, Cc);
    attn_tc<true><<<gA, 128, ATTN_SMEM>>>(q, k, v, a);
    gemm_tc<false, true><<<gP, 128, GEMM_SMEM>>>(a, sa_wo, sa_bo, x, out, Mm, Cc, Cc);

    // ---- cross-attention block ----
    ln_kernel<<<Mm, 256>>>(out, ln2_g, ln2_b, h);
    gemm_tc<false, false><<<gP, 128, GEMM_SMEM>>>(h,   ca_wq, nullptr, nullptr, q, Mm, Cc, Cc);
    gemm_tc<false, false><<<gP, 128, GEMM_SMEM>>>(enc, ca_wk, nullptr, nullptr, k, Mm, Cc, Cc);
    gemm_tc<false, false><<<gP, 128, GEMM_SMEM>>>(enc, ca_wv, nullptr, nullptr, v, Mm, Cc, Cc);
    attn_tc<false><<<gA, 128, ATTN_SMEM>>>(q, k, v, a);
    gemm_tc<false, true><<<gP, 128, GEMM_SMEM>>>(a, ca_wo, ca_bo, out, out, Mm, Cc, Cc);

    // ---- FFN block ----
    ln_kernel<<<Mm, 256>>>(out, ln3_g, ln3_b, h);
    gemm_tc<true,  false><<<gF1, 128, GEMM_SMEM>>>(h,  ff_w1, ff_b1, nullptr, ff, Mm, FF, Cc);
    gemm_tc<false, true><<<gP,  128, GEMM_SMEM>>>(ff, ff_w2, ff_b2, out, out, Mm, Cc, FF);
}

// round 9
// speedup vs baseline: 1.9311x; 1.9311x over previous
#include <cuda_runtime.h>
#include <cuda_fp16.h>
#include <cstdint>
#include <cstddef>

// Problem constants
#define Bb 4
#define Tt 1024
#define Cc 1024
#define Hh 16
#define Dd 64
#define Mm 4096      // B*T tokens
#define FF 4096      // ffn hidden

// ---------------- scratch (device globals; no allocation) ----------------
__device__ __half g_hh[Mm * Cc];        // LN output (fp16)
__device__ __half g_qh[Mm * Cc];
__device__ __half g_kh[Mm * Cc];
__device__ __half g_vh[Mm * Cc];
__device__ __half g_ah[Mm * Cc];        // attention output
__device__ __half g_ffh[Mm * FF];       // FFN hidden (fp16)
__device__ __half g_wch[8 * Cc * Cc];   // 8 CxC weights fp16
__device__ __half g_w1h[Cc * FF];
__device__ __half g_w2h[FF * Cc];
__device__ __half g_ench[Mm * Cc];      // encoder_out fp16

// ---------------- helpers ----------------
__device__ __forceinline__ void cp16(void* dst_smem, const void* src) {
    uint32_t sa = (uint32_t)__cvta_generic_to_shared(dst_smem);
    asm volatile("cp.async.cg.shared.global [%0], [%1], 16;\n" :: "r"(sa), "l"(src));
}
__device__ __forceinline__ void ldsm4(uint32_t r[4], uint32_t a) {
    asm volatile("ldmatrix.sync.aligned.m8n8.x4.shared.b16 {%0,%1,%2,%3}, [%4];"
                 : "=r"(r[0]), "=r"(r[1]), "=r"(r[2]), "=r"(r[3]) : "r"(a));
}
__device__ __forceinline__ void ldsm4t(uint32_t r[4], uint32_t a) {
    asm volatile("ldmatrix.sync.aligned.m8n8.x4.trans.shared.b16 {%0,%1,%2,%3}, [%4];"
                 : "=r"(r[0]), "=r"(r[1]), "=r"(r[2]), "=r"(r[3]) : "r"(a));
}
__device__ __forceinline__ void mma16(float c[4], const uint32_t a[4], const uint32_t b[2]) {
    asm volatile(
        "mma.sync.aligned.m16n8k16.row.col.f32.f16.f16.f32 "
        "{%0,%1,%2,%3}, {%4,%5,%6,%7}, {%8,%9}, {%0,%1,%2,%3};\n"
        : "+f"(c[0]), "+f"(c[1]), "+f"(c[2]), "+f"(c[3])
        : "r"(a[0]), "r"(a[1]), "r"(a[2]), "r"(a[3]), "r"(b[0]), "r"(b[1]));
}
__device__ __forceinline__ uint32_t h2pack(float lo, float hi) {
    __half2 h = __floats2half2_rn(lo, hi);
    return *reinterpret_cast<uint32_t*>(&h);
}

// ---------------- fp32 -> fp16 convert ----------------
__global__ __launch_bounds__(256)
void f2h_kernel(const float* __restrict__ src, __half* __restrict__ dst, int n4) {
    const int i = blockIdx.x * blockDim.x + threadIdx.x;
    if (i < n4) {
        const float4 v = ((const float4*)src)[i];
        ((uint2*)dst)[i] = make_uint2(h2pack(v.x, v.y), h2pack(v.z, v.w));
    }
}

// ---------------- block reduction ----------------
__device__ __forceinline__ float block_sum_256(float v) {
    __shared__ float sh[8];
    const int lane = threadIdx.x & 31;
    const int w = threadIdx.x >> 5;
#pragma unroll
    for (int o = 16; o > 0; o >>= 1) v += __shfl_xor_sync(0xffffffffu, v, o);
    if (lane == 0) sh[w] = v;
    __syncthreads();
    float r = (lane < 8) ? sh[lane] : 0.f;
#pragma unroll
    for (int o = 4; o > 0; o >>= 1) r += __shfl_xor_sync(0xffffffffu, r, o);
    float total = __shfl_sync(0xffffffffu, r, 0);
    __syncthreads();
    return total;
}

// ---------------- layernorm (fp32 in, fp16 out) ----------------
__global__ __launch_bounds__(256)
void ln_kernel(const float* __restrict__ x, const float* __restrict__ g,
               const float* __restrict__ b, __half* __restrict__ out) {
    const size_t row = blockIdx.x;
    const int t = threadIdx.x;
    const float4 v = ((const float4*)(x + row * Cc))[t];
    float s = v.x + v.y + v.z + v.w;
    const float mean = block_sum_256(s) * (1.f / Cc);
    const float dx = v.x - mean, dy = v.y - mean, dz = v.z - mean, dw = v.w - mean;
    const float var = block_sum_256(dx*dx + dy*dy + dz*dz + dw*dw) * (1.f / Cc);
    const float inv = rsqrtf(var + 1e-5f);
    const float4 gg = ((const float4*)g)[t];
    const float4 bb = ((const float4*)b)[t];
    ((uint2*)(out + row * Cc))[t] = make_uint2(
        h2pack(dx * inv * gg.x + bb.x, dy * inv * gg.y + bb.y),
        h2pack(dz * inv * gg.z + bb.z, dw * inv * gg.w + bb.w));
}

// ---------------- fp16 tensor-core GEMM ----------------
// CTA 128x128, 8 warps (2m x 4n), warp 64x32, k-tile 32, 2-stage cp.async.
// A [M,K] fp16, W [K,N] fp16 row-major. acc fp32. ldmatrix frags.
#define GA_P 40                        // A smem pitch (halfs): 80B rows, conflict-free
#define GB_P 136                       // B smem pitch (halfs): 272B rows
#define GA_SZ (128 * GA_P)
#define GB_SZ (32 * GB_P)
#define GSTG (GA_SZ + GB_SZ)
#define GEMM_SMEM (2 * GSTG * 2)       // bytes (37888)

template<bool RELU, bool RES, bool OUTH>
__global__ __launch_bounds__(256, 2)
void gemm_h(const __half* __restrict__ A, const __half* __restrict__ W,
            const float* __restrict__ bias, const float* __restrict__ res,
            void* __restrict__ outp, int M, int N, int K) {
    extern __shared__ __half smh[];
    const uint32_t sbase = (uint32_t)__cvta_generic_to_shared(smh);

    const int m0 = blockIdx.y * 128;
    const int n0 = blockIdx.x * 128;
    const int t = threadIdx.x;
    const int lane = t & 31;
    const int wid = t >> 5;
    const int g = lane >> 2;
    const int tig = lane & 3;
    const int wm = (wid & 1) * 64;
    const int wn = (wid >> 1) * 32;

    float acc[4][4][4];
#pragma unroll
    for (int mi = 0; mi < 4; mi++)
#pragma unroll
        for (int ni = 0; ni < 4; ni++)
#pragma unroll
            for (int r = 0; r < 4; r++) acc[mi][ni][r] = 0.f;

    const int ntk = K >> 5;

    auto load_tile = [&](int kt, int s) {
        __half* As = smh + s * GSTG;
        __half* Bs = As + GA_SZ;
        const int k0 = kt * 32;
#pragma unroll
        for (int i = 0; i < 2; i++) {
            const int idx = t + i * 256;
            const int r = idx >> 2, sg = idx & 3;
            cp16(As + r * GA_P + sg * 8, A + (size_t)(m0 + r) * K + k0 + sg * 8);
        }
#pragma unroll
        for (int i = 0; i < 2; i++) {
            const int idx = t + i * 256;
            const int r = idx >> 4, sg = idx & 15;
            cp16(Bs + r * GB_P + sg * 8, W + (size_t)(k0 + r) * N + n0 + sg * 8);
        }
        asm volatile("cp.async.commit_group;\n");
    };

    load_tile(0, 0);

    for (int kt = 0; kt < ntk; kt++) {
        const int buf = kt & 1;
        if (kt + 1 < ntk) {
            load_tile(kt + 1, buf ^ 1);
            asm volatile("cp.async.wait_group 1;\n");
        } else {
            asm volatile("cp.async.wait_group 0;\n");
        }
        __syncthreads();

        const uint32_t ab = sbase + buf * GSTG * 2;          // A bytes
        const uint32_t bb = ab + GA_SZ * 2;                  // B bytes
#pragma unroll
        for (int ks = 0; ks < 2; ks++) {
            uint32_t af[4][4];
#pragma unroll
            for (int mi = 0; mi < 4; mi++)
                ldsm4(af[mi], ab + ((wm + mi * 16 + (lane & 15)) * GA_P
                                    + ks * 16 + (lane >> 4) * 8) * 2);
            uint32_t bf[4][4];   // [pair][4 regs] -> nfrags 2p:{r0,r1}, 2p+1:{r2,r3}
#pragma unroll
            for (int p = 0; p < 2; p++)
                ldsm4t(bf[p], bb + ((ks * 16 + (lane & 7) + ((lane >> 3) & 1) * 8) * GB_P
                                    + wn + p * 16 + (lane >> 4) * 8) * 2);
#pragma unroll
            for (int mi = 0; mi < 4; mi++)
#pragma unroll
                for (int ni = 0; ni < 4; ni++)
                    mma16(acc[mi][ni], af[mi], &bf[ni >> 1][(ni & 1) * 2]);
        }
        __syncthreads();
    }

    // epilogue
#pragma unroll
    for (int mi = 0; mi < 4; mi++) {
        const int m = m0 + wm + mi * 16 + g;
#pragma unroll
        for (int ni = 0; ni < 4; ni++) {
            const int n = n0 + wn + ni * 8 + tig * 2;
            float v0x = acc[mi][ni][0], v0y = acc[mi][ni][1];
            float v1x = acc[mi][ni][2], v1y = acc[mi][ni][3];
            if (bias) {
                const float b0 = bias[n], b1 = bias[n + 1];
                v0x += b0; v0y += b1; v1x += b0; v1y += b1;
            }
            if (RES) {
                const float2 r0 = *(const float2*)(res + (size_t)m * N + n);
                const float2 r1 = *(const float2*)(res + (size_t)(m + 8) * N + n);
                v0x += r0.x; v0y += r0.y; v1x += r1.x; v1y += r1.y;
            }
            if (RELU) {
                v0x = fmaxf(v0x, 0.f); v0y = fmaxf(v0y, 0.f);
                v1x = fmaxf(v1x, 0.f); v1y = fmaxf(v1y, 0.f);
            }
            if (OUTH) {
                __half* o = (__half*)outp;
                *(uint32_t*)(o + (size_t)m * N + n) = h2pack(v0x, v0y);
                *(uint32_t*)(o + (size_t)(m + 8) * N + n) = h2pack(v1x, v1y);
            } else {
                float* o = (float*)outp;
                *(float2*)(o + (size_t)m * N + n) = make_float2(v0x, v0y);
                *(float2*)(o + (size_t)(m + 8) * N + n) = make_float2(v1x, v1y);
            }
        }
    }
}

// ---------------- fp16 tensor-core flash attention ----------------
// 128 thr (4 warps), warp = 16 q rows, 64-key tiles, double-buffered K/V.
// Q/K/V fp16 [B*T][Cc], head slice h*64. Pitch 72 halfs (144B) conflict-free.
#define AP 72
#define AQ_SZ (64 * AP)                // halfs
#define ATTN_SMEM ((AQ_SZ * 5) * 2)    // Q + 2K + 2V, bytes (46080)

template<bool CAUSAL>
__global__ __launch_bounds__(128)
void attn_h(const __half* __restrict__ Qg, const __half* __restrict__ Kg,
            const __half* __restrict__ Vg, __half* __restrict__ Og) {
    extern __shared__ __half smh[];
    __half* Qs = smh;
    __half* Ks = smh + AQ_SZ;          // [2][64][AP]
    __half* Vs = Ks + 2 * AQ_SZ;       // [2][64][AP]
    const uint32_t sbase = (uint32_t)__cvta_generic_to_shared(smh);
    const uint32_t qb = sbase;
    const uint32_t kb = sbase + AQ_SZ * 2;
    const uint32_t vb = kb + 2 * AQ_SZ * 2;

    const int qt = blockIdx.x;
    const int bh = blockIdx.y;
    const int b = bh >> 4;
    const int h = bh & 15;
    const int q0 = qt * 64;
    const int t = threadIdx.x;
    const int lane = t & 31;
    const int w = t >> 5;
    const int g = lane >> 2;
    const int tig = lane & 3;
    const int wm = w * 16;

    const __half* Qbase = Qg + ((size_t)(b * Tt + q0)) * Cc + h * Dd;
    const __half* Kbase = Kg + ((size_t)(b * Tt)) * Cc + h * Dd;
    const __half* Vbase = Vg + ((size_t)(b * Tt)) * Cc + h * Dd;

    // loaders: 64 rows x 8 segs of 16B; 128 thr x 4
#pragma unroll
    for (int i = 0; i < 4; i++) {
        const int idx = t + i * 128;
        const int r = idx >> 3, sg = idx & 7;
        cp16(Qs + r * AP + sg * 8, Qbase + (size_t)r * Cc + sg * 8);
        cp16(Ks + r * AP + sg * 8, Kbase + (size_t)r * Cc + sg * 8);
        cp16(Vs + r * AP + sg * 8, Vbase + (size_t)r * Cc + sg * 8);
    }
    asm volatile("cp.async.commit_group;\n");

    float m0r = -1e30f, m1r = -1e30f, l0 = 0.f, l1 = 0.f;
    float oacc[8][4];
#pragma unroll
    for (int nf = 0; nf < 8; nf++)
#pragma unroll
        for (int r = 0; r < 4; r++) oacc[nf][r] = 0.f;

    const int ktend = CAUSAL ? qt : (Tt / 64 - 1);
    for (int kt = 0; kt <= ktend; kt++) {
        const int buf = kt & 1;
        if (kt < ktend) {
            const __half* Kp = Kbase + (size_t)(kt + 1) * 64 * Cc;
            const __half* Vp = Vbase + (size_t)(kt + 1) * 64 * Cc;
            __half* Kd = Ks + (buf ^ 1) * AQ_SZ;
            __half* Vd = Vs + (buf ^ 1) * AQ_SZ;
#pragma unroll
            for (int i = 0; i < 4; i++) {
                const int idx = t + i * 128;
                const int r = idx >> 3, sg = idx & 7;
                cp16(Kd + r * AP + sg * 8, Kp + (size_t)r * Cc + sg * 8);
                cp16(Vd + r * AP + sg * 8, Vp + (size_t)r * Cc + sg * 8);
            }
            asm volatile("cp.async.commit_group;\n");
            asm volatile("cp.async.wait_group 1;\n");
        } else {
            asm volatile("cp.async.wait_group 0;\n");
        }
        __syncthreads();

        const uint32_t kbb = kb + buf * AQ_SZ * 2;
        const uint32_t vbb = vb + buf * AQ_SZ * 2;

        // S = Q K^T (fp16 MMA, fp32 accum)
        float sc[8][4];
#pragma unroll
        for (int nf = 0; nf < 8; nf++)
#pragma unroll
            for (int r = 0; r < 4; r++) sc[nf][r] = 0.f;
#pragma unroll
        for (int ks = 0; ks < 4; ks++) {
            uint32_t a[4];
            ldsm4(a, qb + ((wm + (lane & 15)) * AP + ks * 16 + (lane >> 4) * 8) * 2);
#pragma unroll
            for (int p = 0; p < 4; p++) {
                uint32_t bf[4];
                // non-trans: K [key][d] row-major IS the col-major B operand
                ldsm4(bf, kbb + ((p * 16 + (lane >> 4) * 8 + (lane & 7)) * AP
                                 + ks * 16 + ((lane >> 3) & 1) * 8) * 2);
                mma16(sc[2 * p], a, &bf[0]);
                mma16(sc[2 * p + 1], a, &bf[2]);
            }
        }

        // scale + causal mask
        const int r0g = q0 + wm + g;
        const int r1g = r0g + 8;
#pragma unroll
        for (int nf = 0; nf < 8; nf++) {
            sc[nf][0] *= 0.125f; sc[nf][1] *= 0.125f;
            sc[nf][2] *= 0.125f; sc[nf][3] *= 0.125f;
            if (CAUSAL && kt == qt) {
                const int c0 = kt * 64 + nf * 8 + tig * 2;
                if (c0 > r0g) sc[nf][0] = -1e30f;
                if (c0 + 1 > r0g) sc[nf][1] = -1e30f;
                if (c0 > r1g) sc[nf][2] = -1e30f;
                if (c0 + 1 > r1g) sc[nf][3] = -1e30f;
            }
        }

        // online softmax (rows g, g+8); quad (tig) reduction
        float mx0 = -1e30f, mx1 = -1e30f;
#pragma unroll
        for (int nf = 0; nf < 8; nf++) {
            mx0 = fmaxf(mx0, fmaxf(sc[nf][0], sc[nf][1]));
            mx1 = fmaxf(mx1, fmaxf(sc[nf][2], sc[nf][3]));
        }
        mx0 = fmaxf(mx0, __shfl_xor_sync(0xffffffffu, mx0, 1));
        mx0 = fmaxf(mx0, __shfl_xor_sync(0xffffffffu, mx0, 2));
        mx1 = fmaxf(mx1, __shfl_xor_sync(0xffffffffu, mx1, 1));
        mx1 = fmaxf(mx1, __shfl_xor_sync(0xffffffffu, mx1, 2));
        const float nm0 = fmaxf(m0r, mx0);
        const float nm1 = fmaxf(m1r, mx1);
        const float al0 = __expf(m0r - nm0);
        const float al1 = __expf(m1r - nm1);
        float rs0 = 0.f, rs1 = 0.f;
#pragma unroll
        for (int nf = 0; nf < 8; nf++) {
            sc[nf][0] = __expf(sc[nf][0] - nm0);
            sc[nf][1] = __expf(sc[nf][1] - nm0);
            sc[nf][2] = __expf(sc[nf][2] - nm1);
            sc[nf][3] = __expf(sc[nf][3] - nm1);
            rs0 += sc[nf][0] + sc[nf][1];
            rs1 += sc[nf][2] + sc[nf][3];
        }
        rs0 += __shfl_xor_sync(0xffffffffu, rs0, 1);
        rs0 += __shfl_xor_sync(0xffffffffu, rs0, 2);
        rs1 += __shfl_xor_sync(0xffffffffu, rs1, 1);
        rs1 += __shfl_xor_sync(0xffffffffu, rs1, 2);
        l0 = l0 * al0 + rs0;
        l1 = l1 * al1 + rs1;
        m0r = nm0; m1r = nm1;
#pragma unroll
        for (int nf = 0; nf < 8; nf++) {
            oacc[nf][0] *= al0; oacc[nf][1] *= al0;
            oacc[nf][2] *= al1; oacc[nf][3] *= al1;
        }

        // O += P V : P packs directly into A fragments (no smem bounce)
#pragma unroll
        for (int ks = 0; ks < 4; ks++) {
            uint32_t a[4];
            a[0] = h2pack(sc[2 * ks][0], sc[2 * ks][1]);
            a[1] = h2pack(sc[2 * ks][2], sc[2 * ks][3]);
            a[2] = h2pack(sc[2 * ks + 1][0], sc[2 * ks + 1][1]);
            a[3] = h2pack(sc[2 * ks + 1][2], sc[2 * ks + 1][3]);
#pragma unroll
            for (int p = 0; p < 4; p++) {
                uint32_t bf[4];
                // trans: V [key][d] -> col-major [k=key][n=d] fragment
                ldsm4t(bf, vbb + ((ks * 16 + (lane & 7) + ((lane >> 3) & 1) * 8) * AP
                                  + p * 16 + (lane >> 4) * 8) * 2);
                mma16(oacc[2 * p], a, &bf[0]);
                mma16(oacc[2 * p + 1], a, &bf[2]);
            }
        }
        __syncthreads();
    }

    const float inv0 = 1.f / l0;
    const float inv1 = 1.f / l1;
    __half* orow0 = Og + ((size_t)(b * Tt + q0 + wm + g)) * Cc + h * Dd;
    __half* orow1 = orow0 + (size_t)8 * Cc;
#pragma unroll
    for (int nf = 0; nf < 8; nf++) {
        *(uint32_t*)(orow0 + nf * 8 + tig * 2) = h2pack(oacc[nf][0] * inv0, oacc[nf][1] * inv0);
        *(uint32_t*)(orow1 + nf * 8 + tig * 2) = h2pack(oacc[nf][2] * inv1, oacc[nf][3] * inv1);
    }
}

// ---------------- driver ----------------
extern "C" void kernel_launch(void* const* d_in, const int* in_sizes, int n_in,
                              void* d_out, int out_size) {
    const float* x      = (const float*)d_in[0];
    const float* enc    = (const float*)d_in[1];
    const float* sa_wq  = (const float*)d_in[2];
    const float* sa_wk  = (const float*)d_in[3];
    const float* sa_wv  = (const float*)d_in[4];
    const float* sa_wo  = (const float*)d_in[5];
    const float* sa_bo  = (const float*)d_in[6];
    const float* ca_wq  = (const float*)d_in[7];
    const float* ca_wk  = (const float*)d_in[8];
    const float* ca_wv  = (const float*)d_in[9];
    const float* ca_wo  = (const float*)d_in[10];
    const float* ca_bo  = (const float*)d_in[11];
    const float* ff_w1  = (const float*)d_in[12];
    const float* ff_b1  = (const float*)d_in[13];
    const float* ff_w2  = (const float*)d_in[14];
    const float* ff_b2  = (const float*)d_in[15];
    const float* ln1_g  = (const float*)d_in[16];
    const float* ln1_b  = (const float*)d_in[17];
    const float* ln2_g  = (const float*)d_in[18];
    const float* ln2_b  = (const float*)d_in[19];
    const float* ln3_g  = (const float*)d_in[20];
    const float* ln3_b  = (const float*)d_in[21];
    float* out = (float*)d_out;

    __half *hh, *qh, *kh, *vh, *ah, *ffh, *wch, *w1h, *w2h, *ench;
    cudaGetSymbolAddress((void**)&hh,   g_hh);
    cudaGetSymbolAddress((void**)&qh,   g_qh);
    cudaGetSymbolAddress((void**)&kh,   g_kh);
    cudaGetSymbolAddress((void**)&vh,   g_vh);
    cudaGetSymbolAddress((void**)&ah,   g_ah);
    cudaGetSymbolAddress((void**)&ffh,  g_ffh);
    cudaGetSymbolAddress((void**)&wch,  g_wch);
    cudaGetSymbolAddress((void**)&w1h,  g_w1h);
    cudaGetSymbolAddress((void**)&w2h,  g_w2h);
    cudaGetSymbolAddress((void**)&ench, g_ench);

    cudaFuncSetAttribute((const void*)attn_h<true>,
                         cudaFuncAttributeMaxDynamicSharedMemorySize, ATTN_SMEM);
    cudaFuncSetAttribute((const void*)attn_h<false>,
                         cudaFuncAttributeMaxDynamicSharedMemorySize, ATTN_SMEM);
    cudaFuncSetAttribute((const void*)gemm_h<false, false, true>,
                         cudaFuncAttributeMaxDynamicSharedMemorySize, GEMM_SMEM);
    cudaFuncSetAttribute((const void*)gemm_h<false, true, false>,
                         cudaFuncAttributeMaxDynamicSharedMemorySize, GEMM_SMEM);
    cudaFuncSetAttribute((const void*)gemm_h<true, false, true>,
                         cudaFuncAttributeMaxDynamicSharedMemorySize, GEMM_SMEM);

    const int CC = Cc * Cc;           // 1,048,576
    const int CF = Cc * FF;           // 4,194,304
    const int MC = Mm * Cc;           // 4,194,304

    // convert weights + encoder to fp16
    __half* wp[8] = {wch + 0*CC, wch + 1*CC, wch + 2*CC, wch + 3*CC,
                     wch + 4*CC, wch + 5*CC, wch + 6*CC, wch + 7*CC};
    const float* ws[8] = {sa_wq, sa_wk, sa_wv, sa_wo, ca_wq, ca_wk, ca_wv, ca_wo};
    for (int i = 0; i < 8; i++)
        f2h_kernel<<<CC / 4 / 256, 256>>>(ws[i], wp[i], CC / 4);
    f2h_kernel<<<CF / 4 / 256, 256>>>(ff_w1, w1h, CF / 4);
    f2h_kernel<<<CF / 4 / 256, 256>>>(ff_w2, w2h, CF / 4);
    f2h_kernel<<<MC / 4 / 256, 256>>>(enc, ench, MC / 4);

    const dim3 gP(Cc / 128, Mm / 128);     // 8 x 32
    const dim3 gF1(FF / 128, Mm / 128);    // 32 x 32
    const dim3 gA(Tt / 64, Bb * Hh);

    // ---- self-attention block ----
    ln_kernel<<<Mm, 256>>>(x, ln1_g, ln1_b, hh);
    gemm_h<false, false, true><<<gP, 256, GEMM_SMEM>>>(hh, wp[0], nullptr, nullptr, qh, Mm, Cc, Cc);
    gemm_h<false, false, true><<<gP, 256, GEMM_SMEM>>>(hh, wp[1], nullptr, nullptr, kh, Mm, Cc, Cc);
    gemm_h<false, false, true><<<gP, 256, GEMM_SMEM>>>(hh, wp[2], nullptr, nullptr, vh, Mm, Cc, Cc);
    attn_h<true><<<gA, 128, ATTN_SMEM>>>(qh, kh, vh, ah);
    gemm_h<false, true, false><<<gP, 256, GEMM_SMEM>>>(ah, wp[3], sa_bo, x, out, Mm, Cc, Cc);

    // ---- cross-attention block ----
    ln_kernel<<<Mm, 256>>>(out, ln2_g, ln2_b, hh);
    gemm_h<false, false, true><<<gP, 256, GEMM_SMEM>>>(hh,   wp[4], nullptr, nullptr, qh, Mm, Cc, Cc);
    gemm_h<false, false, true><<<gP, 256, GEMM_SMEM>>>(ench, wp[5], nullptr, nullptr, kh, Mm, Cc, Cc);
    gemm_h<false, false, true><<<gP, 256, GEMM_SMEM>>>(ench, wp[6], nullptr, nullptr, vh, Mm, Cc, Cc);
    attn_h<false><<<gA, 128, ATTN_SMEM>>>(qh, kh, vh, ah);
    gemm_h<false, true, false><<<gP, 256, GEMM_SMEM>>>(ah, wp[7], ca_bo, out, out, Mm, Cc, Cc);

    // ---- FFN block ----
    ln_kernel<<<Mm, 256>>>(out, ln3_g, ln3_b, hh);
    gemm_h<true,  false, true><<<gF1, 256, GEMM_SMEM>>>(hh,  w1h, ff_b1, nullptr, ffh, Mm, FF, Cc);
    gemm_h<false, true, false><<<gP,  256, GEMM_SMEM>>>(ffh, w2h, ff_b2, out, out, Mm, Cc, FF);
}